// round 14
// baseline (speedup 1.0000x reference)
#include <cuda_runtime.h>
#include <cuda_fp16.h>
#include <cstdint>

// Problem dims (fixed by the dataset)
#define M_DIM 8192   // B*S
#define N_DIM 4096   // OUT_F
#define K_DIM 4096   // IN_F

// GEMM tiling: CTA 128x128, 4 warps (2m x 2n), warp tile 64x64
#define BM 128
#define BN 128
#define BK 64                      // 64 halves = 128B rows (SW128 atom)
#define KSTEPS (K_DIM / BK)        // 64

// Asymmetric stage rings: A 3-deep, B 4-deep
#define A_ST 16384
#define B_ST 16384
#define A_RING 3
#define B_RING 4
#define B_BASE (A_RING * A_ST)
#define SLOT_OFF (A_RING * A_ST + B_RING * B_ST)     // next-tile broadcast slot
#define SMEM_TOTAL (SLOT_OFF + 16)                   // 112KB+16 -> 2 CTAs/SM

// Persistent grid
#define NTILES_X (N_DIM / BN)      // 32
#define NTILES   ((M_DIM / BM) * NTILES_X)   // 2048
#define GRID_CTAS 304              // 152 SMs x 2 CTAs

// Scratch (no cudaMalloc allowed)
__device__ __half g_W[(size_t)N_DIM * K_DIM];   // 32 MB dequantized weights
__device__ __half g_X[(size_t)M_DIM * K_DIM];   // 64 MB fp16 activations
__device__ int    g_tile_counter = GRID_CTAS;   // dynamic tile pool cursor

// ---------------------------------------------------------------------------
// helpers
// ---------------------------------------------------------------------------
static __device__ __forceinline__ uint32_t s2u(const void* p) {
    uint32_t a;
    asm("{ .reg .u64 t; cvta.to.shared.u64 t, %1; cvt.u32.u64 %0, t; }"
        : "=r"(a) : "l"(p));
    return a;
}

static __device__ __forceinline__ void cp_async16(uint32_t dst, const void* src) {
    asm volatile("cp.async.cg.shared.global [%0], [%1], 16;"
                 :: "r"(dst), "l"(src) : "memory");
}
#define CP_COMMIT() asm volatile("cp.async.commit_group;" ::: "memory")
#define CP_WAIT3()  asm volatile("cp.async.wait_group 3;" ::: "memory")

#define LDSM_X4(r0, r1, r2, r3, a) \
    asm volatile("ldmatrix.sync.aligned.m8n8.x4.shared.b16 {%0,%1,%2,%3}, [%4];" \
                 : "=r"(r0), "=r"(r1), "=r"(r2), "=r"(r3) : "r"(a))

static __device__ __forceinline__ void mma16816(float* c, const uint32_t* a,
                                                const uint32_t* b) {
    asm volatile(
        "mma.sync.aligned.m16n8k16.row.col.f32.f16.f16.f32 "
        "{%0,%1,%2,%3}, {%4,%5,%6,%7}, {%8,%9}, {%0,%1,%2,%3};"
        : "+f"(c[0]), "+f"(c[1]), "+f"(c[2]), "+f"(c[3])
        : "r"(a[0]), "r"(a[1]), "r"(a[2]), "r"(a[3]), "r"(b[0]), "r"(b[1]));
}

// streaming (evict-first) float2 store: keep L2 for the A/B working set
static __device__ __forceinline__ void stg_cs_f2(float* p, float x, float y) {
    asm volatile("st.global.cs.v2.f32 [%0], {%1, %2};"
                 :: "l"(p), "f"(x), "f"(y) : "memory");
}

static __device__ __forceinline__ const char* a_tile_ptr(int T) {
    return (const char*)(g_X + (size_t)((T >> 5) * BM) * K_DIM);
}
static __device__ __forceinline__ const char* b_tile_ptr(int T) {
    return (const char*)(g_W + (size_t)((T & (NTILES_X - 1)) * BN) * K_DIM);
}

// ---------------------------------------------------------------------------
// Fused prep kernel: interleaved dequant (1/3 of blocks) + convert (2/3).
// Measured ~92% of HBM spec — at roofline. Also resets the tile counter
// for the following GEMM launch (graph-replay safe; same-stream ordering).
// ---------------------------------------------------------------------------
#define DEQ_BLOCKS  ((N_DIM * K_DIM) / (256 * 8))            // 8192
#define CVT_BLOCKS  (((size_t)M_DIM * K_DIM) / (256 * 8))    // 16384
#define PREP_BLOCKS (DEQ_BLOCKS + CVT_BLOCKS)                // 24576

__global__ void prep_kernel(const float* __restrict__ x,
                            const int* __restrict__ idx,
                            const float* __restrict__ scale,
                            const float* __restrict__ lut) {
    int b = blockIdx.x;
    if (b == 0 && threadIdx.x == 0) g_tile_counter = GRID_CTAS;
    int r3 = b % 3;
    if (r3 == 2) {
        int db = b / 3;
        size_t base = ((size_t)db * 256 + threadIdx.x) * 8;
        int row = (int)(base / K_DIM);
        float s = scale[row];
        int4 c0 = *reinterpret_cast<const int4*>(idx + base);
        int4 c1 = *reinterpret_cast<const int4*>(idx + base + 4);
        __half2 h[4];
        h[0] = __floats2half2_rn(lut[c0.x] * s, lut[c0.y] * s);
        h[1] = __floats2half2_rn(lut[c0.z] * s, lut[c0.w] * s);
        h[2] = __floats2half2_rn(lut[c1.x] * s, lut[c1.y] * s);
        h[3] = __floats2half2_rn(lut[c1.z] * s, lut[c1.w] * s);
        *reinterpret_cast<uint4*>(g_W + base) = *reinterpret_cast<uint4*>(h);
    } else {
        int cb = (b / 3) * 2 + r3;
        size_t base = ((size_t)cb * 256 + threadIdx.x) * 8;
        float4 v0 = *reinterpret_cast<const float4*>(x + base);
        float4 v1 = *reinterpret_cast<const float4*>(x + base + 4);
        __half2 h[4];
        h[0] = __floats2half2_rn(v0.x, v0.y);
        h[1] = __floats2half2_rn(v0.z, v0.w);
        h[2] = __floats2half2_rn(v1.x, v1.y);
        h[3] = __floats2half2_rn(v1.z, v1.w);
        *reinterpret_cast<uint4*>(g_X + base) = *reinterpret_cast<uint4*>(h);
    }
}

// ---------------------------------------------------------------------------
// Persistent HMMA GEMM, asymmetric A(3)/B(4) cp.async rings, DYNAMIC tile
// scheduling (atomic pool) to kill the 224x7/80x6 static-assignment tail.
// Mainloop instruction schedule is the R9/R13 measured-best, byte-identical:
// q0 prefetch clump -> A-refill commit -> per q {8-LDSM clump for q+1,
// B-refill commit at q==0, 32 MMAs}. DO NOT reorder (R11/R12 regressed).
//   out[m,n] = sum_k X[m,k] * W[n,k]
// ---------------------------------------------------------------------------
__device__ __forceinline__ void load_half(int tid, uint32_t S, const char* Gk) {
    const size_t krow = (size_t)K_DIM * 2;   // row stride bytes
    #pragma unroll
    for (int j = 0; j < 8; j++) {
        int cid = tid + 128 * j;
        int row = cid >> 3;
        int c   = cid & 7;
        uint32_t sw = (uint32_t)(row * 128 + ((c ^ (row & 7)) * 16));
        cp_async16(S + sw, Gk + (size_t)row * krow + c * 16);
    }
}

__global__ void __launch_bounds__(128, 2)
gemm_hmma_kernel(float* __restrict__ out) {
    extern __shared__ __align__(1024) char smem[];
    const uint32_t sb  = s2u(smem);
    const uint32_t sbB = sb + B_BASE;
    int* const slot = reinterpret_cast<int*>(smem + SLOT_OFF);
    const int tid = threadIdx.x;
    const int wid = tid >> 5;
    const int lid = tid & 31;
    const int wm = wid & 1;
    const int wn = wid >> 1;

    // per-lane ldmatrix address components (stage-relative, tile-invariant)
    uint32_t a_rowoff[4], b_rowoff[4];
    #pragma unroll
    for (int i = 0; i < 4; i++)
        a_rowoff[i] = (uint32_t)((wm * 64 + i * 16 + (lid & 15)) * 128);
    #pragma unroll
    for (int j2 = 0; j2 < 4; j2++)
        b_rowoff[j2] = (uint32_t)((wn * 64 + j2 * 16 + (lid & 7) +
                                   ((lid >> 4) & 1) * 8) * 128);
    uint32_t a_ch[4], b_ch[4];
    #pragma unroll
    for (int q = 0; q < 4; q++) {
        a_ch[q] = (uint32_t)((((2 * q + (lid >> 4)) ^ (lid & 7)) * 16));
        b_ch[q] = (uint32_t)((((2 * q + ((lid >> 3) & 1)) ^ (lid & 7)) * 16));
    }

    float acc[4][8][4];
    #pragma unroll
    for (int i = 0; i < 4; i++)
        #pragma unroll
        for (int j = 0; j < 8; j++)
            #pragma unroll
            for (int r = 0; r < 4; r++)
                acc[i][j][r] = 0.0f;

    int T = blockIdx.x;   // first tile: static; subsequent: atomic pool

    // Prologue: A ksteps 0,1 and B ksteps 0,1,2
    {
        const char* A0 = a_tile_ptr(T);
        const char* B0 = b_tile_ptr(T);
        load_half(tid, sb  + 0 * A_ST, A0);          CP_COMMIT();
        load_half(tid, sbB + 0 * B_ST, B0);          CP_COMMIT();
        load_half(tid, sb  + 1 * A_ST, A0 + 128);    CP_COMMIT();
        load_half(tid, sbB + 1 * B_ST, B0 + 128);    CP_COMMIT();
        load_half(tid, sbB + 2 * B_ST, B0 + 256);    CP_COMMIT();
    }

    const char* rA = a_tile_ptr(T) + 2 * 128;
    const char* rB = b_tile_ptr(T) + 3 * 128;
    bool liveA = true, liveB = true;

    uint32_t a_frag[2][4][4];
    uint32_t b_frag[2][4][4];
    int sA_cur = 0, sA_nxt = 2;    // mod 3
    int sB_cur = 0, sB_nxt = 3;    // mod 4

    #pragma unroll 1
    while (true) {
        int Tn = NTILES;           // next tile (read from slot at i==61)

        #pragma unroll 1
        for (int i = 0; i < KSTEPS; i++) {
            CP_WAIT3();
            __syncthreads();

            // grab the NEXT tile early (visible by the i>=1 syncthreads)
            if (i == 0 && tid == 0)
                *slot = atomicAdd(&g_tile_counter, 1);

            const uint32_t SA  = sb  + sA_cur * A_ST;
            const uint32_t SB  = sbB + sB_cur * B_ST;
            const uint32_t SAX = sb  + sA_nxt * A_ST;
            const uint32_t SBX = sbB + sB_nxt * B_ST;

            if (i == KSTEPS - 3) {            // B horizon: refill -> next kstep 0
                Tn = *slot;
                if (Tn < NTILES) { rB = b_tile_ptr(Tn); }
                else             { liveB = false; }
            }
            if (i == KSTEPS - 2) {            // A horizon
                if (Tn < NTILES) { rA = a_tile_ptr(Tn); }
                else             { liveA = false; }
            }

            // q0 fragment prefetch FIRST: start the MMA dependency chain
            #pragma unroll
            for (int t4 = 0; t4 < 4; t4++)
                LDSM_X4(a_frag[0][t4][0], a_frag[0][t4][1],
                        a_frag[0][t4][2], a_frag[0][t4][3],
                        SA + a_rowoff[t4] + a_ch[0]);
            #pragma unroll
            for (int j2 = 0; j2 < 4; j2++)
                LDSM_X4(b_frag[0][j2][0], b_frag[0][j2][1],
                        b_frag[0][j2][2], b_frag[0][j2][3],
                        SB + b_rowoff[j2] + b_ch[0]);

            // A-refill group (for kstep i+2); ALWAYS commit for accounting
            if (liveA) load_half(tid, SAX, rA);
            CP_COMMIT();

            #pragma unroll
            for (int q = 0; q < 4; q++) {
                const int cur = q & 1, nxt = cur ^ 1;
                if (q < 3) {
                    #pragma unroll
                    for (int t4 = 0; t4 < 4; t4++)
                        LDSM_X4(a_frag[nxt][t4][0], a_frag[nxt][t4][1],
                                a_frag[nxt][t4][2], a_frag[nxt][t4][3],
                                SA + a_rowoff[t4] + a_ch[q + 1]);
                    #pragma unroll
                    for (int j2 = 0; j2 < 4; j2++)
                        LDSM_X4(b_frag[nxt][j2][0], b_frag[nxt][j2][1],
                                b_frag[nxt][j2][2], b_frag[nxt][j2][3],
                                SB + b_rowoff[j2] + b_ch[q + 1]);
                }
                if (q == 0) {
                    // B-refill group (for kstep i+3); ALWAYS commit
                    if (liveB) load_half(tid, SBX, rB);
                    CP_COMMIT();
                }
                #pragma unroll
                for (int t4 = 0; t4 < 4; t4++)
                    #pragma unroll
                    for (int j = 0; j < 8; j++)
                        mma16816(acc[t4][j], a_frag[cur][t4],
                                 &b_frag[cur][j >> 1][(j & 1) * 2]);
            }

            rA += 128;
            rB += 128;
            sA_cur = (sA_cur == A_RING - 1) ? 0 : sA_cur + 1;
            sA_nxt = (sA_nxt == A_RING - 1) ? 0 : sA_nxt + 1;
            sB_cur = (sB_cur == B_RING - 1) ? 0 : sB_cur + 1;
            sB_nxt = (sB_nxt == B_RING - 1) ? 0 : sB_nxt + 1;
        }

        // Epilogue for tile T: evict-first stores (write-once data)
        {
            const int m0 = (T >> 5) * BM;
            const int n0 = (T & (NTILES_X - 1)) * BN;
            const int g  = lid >> 2;
            const int tc = lid & 3;
            float* Cb = out + (size_t)(m0 + wm * 64) * N_DIM + n0 + wn * 64;
            #pragma unroll
            for (int t4 = 0; t4 < 4; t4++) {
                #pragma unroll
                for (int j = 0; j < 8; j++) {
                    float* p0 = Cb + (size_t)(t4 * 16 + g) * N_DIM + j * 8 + tc * 2;
                    float* p1 = p0 + 8 * N_DIM;
                    stg_cs_f2(p0, acc[t4][j][0], acc[t4][j][1]);
                    stg_cs_f2(p1, acc[t4][j][2], acc[t4][j][3]);
                    acc[t4][j][0] = 0.0f; acc[t4][j][1] = 0.0f;
                    acc[t4][j][2] = 0.0f; acc[t4][j][3] = 0.0f;
                }
            }
        }

        if (Tn >= NTILES) break;
        T = Tn;
    }
}

// ---------------------------------------------------------------------------
// Entry point. Inputs: x f32, grid_indices i32, scale f32, lut f32.
// Output: float32 [8192, 4096].
// ---------------------------------------------------------------------------
extern "C" void kernel_launch(void* const* d_in, const int* in_sizes, int n_in,
                              void* d_out, int out_size) {
    const float* x     = (const float*)d_in[0];
    const int*   idx   = (const int*)  d_in[1];
    const float* scale = (const float*)d_in[2];
    const float* lut   = (const float*)d_in[3];
    float* out = (float*)d_out;

    prep_kernel<<<PREP_BLOCKS, 256>>>(x, idx, scale, lut);

    cudaFuncSetAttribute(gemm_hmma_kernel,
                         cudaFuncAttributeMaxDynamicSharedMemorySize, SMEM_TOTAL);
    gemm_hmma_kernel<<<GRID_CTAS, 128, SMEM_TOTAL>>>(out);
}

// round 15
// speedup vs baseline: 1.1285x; 1.1285x over previous
#include <cuda_runtime.h>
#include <cuda_fp16.h>
#include <cstdint>

// Problem dims (fixed by the dataset)
#define M_DIM 8192   // B*S
#define N_DIM 4096   // OUT_F
#define K_DIM 4096   // IN_F

// GEMM tiling: CTA 128x128, 4 warps (2m x 2n), warp tile 64x64
#define BM 128
#define BN 128
#define BK 64                      // 64 halves = 128B rows (SW128 atom)
#define KSTEPS (K_DIM / BK)        // 64

// Asymmetric stage rings: A 3-deep, B 4-deep
#define A_ST 16384
#define B_ST 16384
#define A_RING 3
#define B_RING 4
#define B_BASE (A_RING * A_ST)
#define SMEM_TOTAL (A_RING * A_ST + B_RING * B_ST)   // 112KB -> 2 CTAs/SM

// Persistent grid
#define NTILES_X (N_DIM / BN)      // 32
#define NTILES   ((M_DIM / BM) * NTILES_X)   // 2048
#define GRID_CTAS 304              // 152 SMs x 2 CTAs

// Scratch (no cudaMalloc allowed)
__device__ __half g_W[(size_t)N_DIM * K_DIM];   // 32 MB dequantized weights
__device__ __half g_X[(size_t)M_DIM * K_DIM];   // 64 MB fp16 activations

// ---------------------------------------------------------------------------
// helpers
// ---------------------------------------------------------------------------
static __device__ __forceinline__ uint32_t s2u(const void* p) {
    uint32_t a;
    asm("{ .reg .u64 t; cvta.to.shared.u64 t, %1; cvt.u32.u64 %0, t; }"
        : "=r"(a) : "l"(p));
    return a;
}

static __device__ __forceinline__ void cp_async16(uint32_t dst, const void* src) {
    asm volatile("cp.async.cg.shared.global [%0], [%1], 16;"
                 :: "r"(dst), "l"(src) : "memory");
}
#define CP_COMMIT() asm volatile("cp.async.commit_group;" ::: "memory")
#define CP_WAIT3()  asm volatile("cp.async.wait_group 3;" ::: "memory")

#define LDSM_X4(r0, r1, r2, r3, a) \
    asm volatile("ldmatrix.sync.aligned.m8n8.x4.shared.b16 {%0,%1,%2,%3}, [%4];" \
                 : "=r"(r0), "=r"(r1), "=r"(r2), "=r"(r3) : "r"(a))

static __device__ __forceinline__ void mma16816(float* c, const uint32_t* a,
                                                const uint32_t* b) {
    asm volatile(
        "mma.sync.aligned.m16n8k16.row.col.f32.f16.f16.f32 "
        "{%0,%1,%2,%3}, {%4,%5,%6,%7}, {%8,%9}, {%0,%1,%2,%3};"
        : "+f"(c[0]), "+f"(c[1]), "+f"(c[2]), "+f"(c[3])
        : "r"(a[0]), "r"(a[1]), "r"(a[2]), "r"(a[3]), "r"(b[0]), "r"(b[1]));
}

static __device__ __forceinline__ const char* a_tile_ptr(int T) {
    return (const char*)(g_X + (size_t)((T >> 5) * BM) * K_DIM);
}
static __device__ __forceinline__ const char* b_tile_ptr(int T) {
    return (const char*)(g_W + (size_t)((T & (NTILES_X - 1)) * BN) * K_DIM);
}

// ---------------------------------------------------------------------------
// Fused prep kernel: interleaved dequant (1/3 of blocks) + convert (2/3).
// Measured ~92% of HBM spec — at roofline; unchanged.
// ---------------------------------------------------------------------------
#define DEQ_BLOCKS  ((N_DIM * K_DIM) / (256 * 8))            // 8192
#define CVT_BLOCKS  (((size_t)M_DIM * K_DIM) / (256 * 8))    // 16384
#define PREP_BLOCKS (DEQ_BLOCKS + CVT_BLOCKS)                // 24576

__global__ void prep_kernel(const float* __restrict__ x,
                            const int* __restrict__ idx,
                            const float* __restrict__ scale,
                            const float* __restrict__ lut) {
    int b = blockIdx.x;
    int r3 = b % 3;
    if (r3 == 2) {
        int db = b / 3;
        size_t base = ((size_t)db * 256 + threadIdx.x) * 8;
        int row = (int)(base / K_DIM);
        float s = scale[row];
        int4 c0 = *reinterpret_cast<const int4*>(idx + base);
        int4 c1 = *reinterpret_cast<const int4*>(idx + base + 4);
        __half2 h[4];
        h[0] = __floats2half2_rn(lut[c0.x] * s, lut[c0.y] * s);
        h[1] = __floats2half2_rn(lut[c0.z] * s, lut[c0.w] * s);
        h[2] = __floats2half2_rn(lut[c1.x] * s, lut[c1.y] * s);
        h[3] = __floats2half2_rn(lut[c1.z] * s, lut[c1.w] * s);
        *reinterpret_cast<uint4*>(g_W + base) = *reinterpret_cast<uint4*>(h);
    } else {
        int cb = (b / 3) * 2 + r3;
        size_t base = ((size_t)cb * 256 + threadIdx.x) * 8;
        float4 v0 = *reinterpret_cast<const float4*>(x + base);
        float4 v1 = *reinterpret_cast<const float4*>(x + base + 4);
        __half2 h[4];
        h[0] = __floats2half2_rn(v0.x, v0.y);
        h[1] = __floats2half2_rn(v0.z, v0.w);
        h[2] = __floats2half2_rn(v1.x, v1.y);
        h[3] = __floats2half2_rn(v1.z, v1.w);
        *reinterpret_cast<uint4*>(g_X + base) = *reinterpret_cast<uint4*>(h);
    }
}

// ---------------------------------------------------------------------------
// Persistent HMMA GEMM, asymmetric A(3)/B(4) cp.async rings. EXACT R9
// measured-best (571.7us). Per kstep i: commit group {A-refill for kstep
// i+2}, then {B-refill for kstep i+3} at q==0. wait_group 3 at the kstep
// head. Static tile map (x-major => W L2-resident), continuous ring across
// tile boundaries, epilogue overlapped. DO NOT perturb: R11 (interleave),
// R12 (refill move), R14 (dynamic sched) all regressed 10-19%.
//   out[m,n] = sum_k X[m,k] * W[n,k]
// ---------------------------------------------------------------------------
__device__ __forceinline__ void load_half(int tid, uint32_t S, const char* Gk) {
    const size_t krow = (size_t)K_DIM * 2;   // row stride bytes
    #pragma unroll
    for (int j = 0; j < 8; j++) {
        int cid = tid + 128 * j;
        int row = cid >> 3;
        int c   = cid & 7;
        uint32_t sw = (uint32_t)(row * 128 + ((c ^ (row & 7)) * 16));
        cp_async16(S + sw, Gk + (size_t)row * krow + c * 16);
    }
}

__global__ void __launch_bounds__(128, 2)
gemm_hmma_kernel(float* __restrict__ out) {
    extern __shared__ __align__(1024) char smem[];
    const uint32_t sb  = s2u(smem);
    const uint32_t sbB = sb + B_BASE;
    const int tid = threadIdx.x;
    const int wid = tid >> 5;
    const int lid = tid & 31;
    const int wm = wid & 1;
    const int wn = wid >> 1;

    // per-lane ldmatrix address components (stage-relative, tile-invariant)
    uint32_t a_rowoff[4], b_rowoff[4];
    #pragma unroll
    for (int i = 0; i < 4; i++)
        a_rowoff[i] = (uint32_t)((wm * 64 + i * 16 + (lid & 15)) * 128);
    #pragma unroll
    for (int j2 = 0; j2 < 4; j2++)
        b_rowoff[j2] = (uint32_t)((wn * 64 + j2 * 16 + (lid & 7) +
                                   ((lid >> 4) & 1) * 8) * 128);
    uint32_t a_ch[4], b_ch[4];
    #pragma unroll
    for (int q = 0; q < 4; q++) {
        a_ch[q] = (uint32_t)((((2 * q + (lid >> 4)) ^ (lid & 7)) * 16));
        b_ch[q] = (uint32_t)((((2 * q + ((lid >> 3) & 1)) ^ (lid & 7)) * 16));
    }

    float acc[4][8][4];
    #pragma unroll
    for (int i = 0; i < 4; i++)
        #pragma unroll
        for (int j = 0; j < 8; j++)
            #pragma unroll
            for (int r = 0; r < 4; r++)
                acc[i][j][r] = 0.0f;

    const int T0 = blockIdx.x;

    // Prologue: A ksteps 0,1 and B ksteps 0,1,2
    {
        const char* A0 = a_tile_ptr(T0);
        const char* B0 = b_tile_ptr(T0);
        load_half(tid, sb  + 0 * A_ST, A0);          CP_COMMIT();
        load_half(tid, sbB + 0 * B_ST, B0);          CP_COMMIT();
        load_half(tid, sb  + 1 * A_ST, A0 + 128);    CP_COMMIT();
        load_half(tid, sbB + 1 * B_ST, B0 + 128);    CP_COMMIT();
        load_half(tid, sbB + 2 * B_ST, B0 + 256);    CP_COMMIT();
    }

    const char* rA = a_tile_ptr(T0) + 2 * 128;
    const char* rB = b_tile_ptr(T0) + 3 * 128;
    bool liveA = true, liveB = true;

    uint32_t a_frag[2][4][4];
    uint32_t b_frag[2][4][4];
    int sA_cur = 0, sA_nxt = 2;    // mod 3
    int sB_cur = 0, sB_nxt = 3;    // mod 4

    #pragma unroll 1
    for (int T = T0; T < NTILES; T += GRID_CTAS) {
        const bool has_next = (T + GRID_CTAS) < NTILES;
        const char* AgN = has_next ? a_tile_ptr(T + GRID_CTAS) : rA;
        const char* BgN = has_next ? b_tile_ptr(T + GRID_CTAS) : rB;

        #pragma unroll 1
        for (int i = 0; i < KSTEPS; i++) {
            CP_WAIT3();
            __syncthreads();

            const uint32_t SA  = sb  + sA_cur * A_ST;
            const uint32_t SB  = sbB + sB_cur * B_ST;
            const uint32_t SAX = sb  + sA_nxt * A_ST;
            const uint32_t SBX = sbB + sB_nxt * B_ST;

            if (i == KSTEPS - 2) { rA = AgN; liveA = has_next; }   // A(i+2)
            if (i == KSTEPS - 3) { rB = BgN; liveB = has_next; }   // B(i+3)

            // q0 fragment prefetch FIRST: start the MMA dependency chain
            #pragma unroll
            for (int t4 = 0; t4 < 4; t4++)
                LDSM_X4(a_frag[0][t4][0], a_frag[0][t4][1],
                        a_frag[0][t4][2], a_frag[0][t4][3],
                        SA + a_rowoff[t4] + a_ch[0]);
            #pragma unroll
            for (int j2 = 0; j2 < 4; j2++)
                LDSM_X4(b_frag[0][j2][0], b_frag[0][j2][1],
                        b_frag[0][j2][2], b_frag[0][j2][3],
                        SB + b_rowoff[j2] + b_ch[0]);

            // A-refill group (for kstep i+2); ALWAYS commit for accounting
            if (liveA) load_half(tid, SAX, rA);
            CP_COMMIT();

            #pragma unroll
            for (int q = 0; q < 4; q++) {
                const int cur = q & 1, nxt = cur ^ 1;
                if (q < 3) {
                    #pragma unroll
                    for (int t4 = 0; t4 < 4; t4++)
                        LDSM_X4(a_frag[nxt][t4][0], a_frag[nxt][t4][1],
                                a_frag[nxt][t4][2], a_frag[nxt][t4][3],
                                SA + a_rowoff[t4] + a_ch[q + 1]);
                    #pragma unroll
                    for (int j2 = 0; j2 < 4; j2++)
                        LDSM_X4(b_frag[nxt][j2][0], b_frag[nxt][j2][1],
                                b_frag[nxt][j2][2], b_frag[nxt][j2][3],
                                SB + b_rowoff[j2] + b_ch[q + 1]);
                }
                if (q == 0) {
                    // B-refill group (for kstep i+3); ALWAYS commit
                    if (liveB) load_half(tid, SBX, rB);
                    CP_COMMIT();
                }
                #pragma unroll
                for (int t4 = 0; t4 < 4; t4++)
                    #pragma unroll
                    for (int j = 0; j < 8; j++)
                        mma16816(acc[t4][j], a_frag[cur][t4],
                                 &b_frag[cur][j >> 1][(j & 1) * 2]);
            }

            rA += 128;
            rB += 128;
            sA_cur = (sA_cur == A_RING - 1) ? 0 : sA_cur + 1;
            sA_nxt = (sA_nxt == A_RING - 1) ? 0 : sA_nxt + 1;
            sB_cur = (sB_cur == B_RING - 1) ? 0 : sB_cur + 1;
            sB_nxt = (sB_nxt == B_RING - 1) ? 0 : sB_nxt + 1;
        }

        // Epilogue for tile T (overlaps the next tile's in-flight loads)
        {
            const int m0 = (T >> 5) * BM;
            const int n0 = (T & (NTILES_X - 1)) * BN;
            const int g  = lid >> 2;
            const int tc = lid & 3;
            float* Cb = out + (size_t)(m0 + wm * 64) * N_DIM + n0 + wn * 64;
            #pragma unroll
            for (int t4 = 0; t4 < 4; t4++) {
                #pragma unroll
                for (int j = 0; j < 8; j++) {
                    float* p0 = Cb + (size_t)(t4 * 16 + g) * N_DIM + j * 8 + tc * 2;
                    float* p1 = p0 + 8 * N_DIM;
                    *reinterpret_cast<float2*>(p0) =
                        make_float2(acc[t4][j][0], acc[t4][j][1]);
                    *reinterpret_cast<float2*>(p1) =
                        make_float2(acc[t4][j][2], acc[t4][j][3]);
                    acc[t4][j][0] = 0.0f; acc[t4][j][1] = 0.0f;
                    acc[t4][j][2] = 0.0f; acc[t4][j][3] = 0.0f;
                }
            }
        }
    }
}

// ---------------------------------------------------------------------------
// Entry point. Inputs: x f32, grid_indices i32, scale f32, lut f32.
// Output: float32 [8192, 4096].
// ---------------------------------------------------------------------------
extern "C" void kernel_launch(void* const* d_in, const int* in_sizes, int n_in,
                              void* d_out, int out_size) {
    const float* x     = (const float*)d_in[0];
    const int*   idx   = (const int*)  d_in[1];
    const float* scale = (const float*)d_in[2];
    const float* lut   = (const float*)d_in[3];
    float* out = (float*)d_out;

    prep_kernel<<<PREP_BLOCKS, 256>>>(x, idx, scale, lut);

    cudaFuncSetAttribute(gemm_hmma_kernel,
                         cudaFuncAttributeMaxDynamicSharedMemorySize, SMEM_TOTAL);
    gemm_hmma_kernel<<<GRID_CTAS, 128, SMEM_TOTAL>>>(out);
}

// round 16
// speedup vs baseline: 1.1297x; 1.0010x over previous
#include <cuda_runtime.h>
#include <cuda_fp16.h>
#include <cstdint>

// Problem dims (fixed by the dataset)
#define M_DIM 8192   // B*S
#define N_DIM 4096   // OUT_F
#define K_DIM 4096   // IN_F

// GEMM tiling: CTA 128x128, 4 warps (2m x 2n), warp tile 64x64
#define BM 128
#define BN 128
#define BK 64                      // 64 halves = 128B rows (SW128 atom)
#define KSTEPS (K_DIM / BK)        // 64

// Asymmetric stage rings: A 3-deep, B 4-deep
#define A_ST 16384
#define B_ST 16384
#define A_RING 3
#define B_RING 4
#define B_BASE (A_RING * A_ST)
#define SMEM_TOTAL (A_RING * A_ST + B_RING * B_ST)   // 112KB -> 2 CTAs/SM

// Persistent grid
#define NTILES_X (N_DIM / BN)      // 32
#define NTILES   ((M_DIM / BM) * NTILES_X)   // 2048
#define GRID_CTAS 304              // 152 SMs x 2 CTAs

// Scratch (no cudaMalloc allowed)
__device__ __half g_W[(size_t)N_DIM * K_DIM];   // 32 MB dequantized weights
__device__ __half g_X[(size_t)M_DIM * K_DIM];   // 64 MB fp16 activations

// ---------------------------------------------------------------------------
// helpers
// ---------------------------------------------------------------------------
static __device__ __forceinline__ uint32_t s2u(const void* p) {
    uint32_t a;
    asm("{ .reg .u64 t; cvta.to.shared.u64 t, %1; cvt.u32.u64 %0, t; }"
        : "=r"(a) : "l"(p));
    return a;
}

static __device__ __forceinline__ void cp_async16(uint32_t dst, const void* src) {
    asm volatile("cp.async.cg.shared.global [%0], [%1], 16;"
                 :: "r"(dst), "l"(src) : "memory");
}
#define CP_COMMIT() asm volatile("cp.async.commit_group;" ::: "memory")
#define CP_WAIT3()  asm volatile("cp.async.wait_group 3;" ::: "memory")

#define LDSM_X4(r0, r1, r2, r3, a) \
    asm volatile("ldmatrix.sync.aligned.m8n8.x4.shared.b16 {%0,%1,%2,%3}, [%4];" \
                 : "=r"(r0), "=r"(r1), "=r"(r2), "=r"(r3) : "r"(a))

static __device__ __forceinline__ void mma16816(float* c, const uint32_t* a,
                                                const uint32_t* b) {
    asm volatile(
        "mma.sync.aligned.m16n8k16.row.col.f32.f16.f16.f32 "
        "{%0,%1,%2,%3}, {%4,%5,%6,%7}, {%8,%9}, {%0,%1,%2,%3};"
        : "+f"(c[0]), "+f"(c[1]), "+f"(c[2]), "+f"(c[3])
        : "r"(a[0]), "r"(a[1]), "r"(a[2]), "r"(a[3]), "r"(b[0]), "r"(b[1]));
}

static __device__ __forceinline__ const char* a_tile_ptr(int T) {
    return (const char*)(g_X + (size_t)((T >> 5) * BM) * K_DIM);
}
static __device__ __forceinline__ const char* b_tile_ptr(int T) {
    return (const char*)(g_W + (size_t)((T & (NTILES_X - 1)) * BN) * K_DIM);
}

// ---------------------------------------------------------------------------
// Fused prep kernel: interleaved dequant (1/3 of blocks) + convert (2/3).
// Block ratio 1:2 matches the 96MB:192MB traffic split. Measured ~92% of
// HBM spec — at the memory roofline.
// ---------------------------------------------------------------------------
#define DEQ_BLOCKS  ((N_DIM * K_DIM) / (256 * 8))            // 8192
#define CVT_BLOCKS  (((size_t)M_DIM * K_DIM) / (256 * 8))    // 16384
#define PREP_BLOCKS (DEQ_BLOCKS + CVT_BLOCKS)                // 24576

__global__ void prep_kernel(const float* __restrict__ x,
                            const int* __restrict__ idx,
                            const float* __restrict__ scale,
                            const float* __restrict__ lut) {
    int b = blockIdx.x;
    int r3 = b % 3;
    if (r3 == 2) {
        int db = b / 3;
        size_t base = ((size_t)db * 256 + threadIdx.x) * 8;
        int row = (int)(base / K_DIM);
        float s = scale[row];
        int4 c0 = *reinterpret_cast<const int4*>(idx + base);
        int4 c1 = *reinterpret_cast<const int4*>(idx + base + 4);
        __half2 h[4];
        h[0] = __floats2half2_rn(lut[c0.x] * s, lut[c0.y] * s);
        h[1] = __floats2half2_rn(lut[c0.z] * s, lut[c0.w] * s);
        h[2] = __floats2half2_rn(lut[c1.x] * s, lut[c1.y] * s);
        h[3] = __floats2half2_rn(lut[c1.z] * s, lut[c1.w] * s);
        *reinterpret_cast<uint4*>(g_W + base) = *reinterpret_cast<uint4*>(h);
    } else {
        int cb = (b / 3) * 2 + r3;
        size_t base = ((size_t)cb * 256 + threadIdx.x) * 8;
        float4 v0 = *reinterpret_cast<const float4*>(x + base);
        float4 v1 = *reinterpret_cast<const float4*>(x + base + 4);
        __half2 h[4];
        h[0] = __floats2half2_rn(v0.x, v0.y);
        h[1] = __floats2half2_rn(v0.z, v0.w);
        h[2] = __floats2half2_rn(v1.x, v1.y);
        h[3] = __floats2half2_rn(v1.z, v1.w);
        *reinterpret_cast<uint4*>(g_X + base) = *reinterpret_cast<uint4*>(h);
    }
}

// ---------------------------------------------------------------------------
// Persistent HMMA GEMM, asymmetric A(3)/B(4) cp.async rings. MEASURED-BEST
// configuration (571.7us across four confirmation benches). Per kstep i:
// wait_group 3 + barrier; q0 prefetch clump; A-refill commit (kstep i+2);
// per q: 8-LDSM clump for q+1, B-refill commit at q==0 (kstep i+3), 32 MMAs.
// Static x-major tile map keeps the 32MB W matrix L2-resident (DRAM 5%).
// Continuous ring across tile boundaries; epilogue overlaps next tile loads.
// DO NOT perturb the schedule: R11 (fine interleave), R12 (refill at q==1),
// R14 (dynamic scheduling) all regressed 10-19%; R8/R10 variants neutral.
//   out[m,n] = sum_k X[m,k] * W[n,k]
// ---------------------------------------------------------------------------
__device__ __forceinline__ void load_half(int tid, uint32_t S, const char* Gk) {
    const size_t krow = (size_t)K_DIM * 2;   // row stride bytes
    #pragma unroll
    for (int j = 0; j < 8; j++) {
        int cid = tid + 128 * j;
        int row = cid >> 3;
        int c   = cid & 7;
        uint32_t sw = (uint32_t)(row * 128 + ((c ^ (row & 7)) * 16));
        cp_async16(S + sw, Gk + (size_t)row * krow + c * 16);
    }
}

__global__ void __launch_bounds__(128, 2)
gemm_hmma_kernel(float* __restrict__ out) {
    extern __shared__ __align__(1024) char smem[];
    const uint32_t sb  = s2u(smem);
    const uint32_t sbB = sb + B_BASE;
    const int tid = threadIdx.x;
    const int wid = tid >> 5;
    const int lid = tid & 31;
    const int wm = wid & 1;
    const int wn = wid >> 1;

    // per-lane ldmatrix address components (stage-relative, tile-invariant)
    uint32_t a_rowoff[4], b_rowoff[4];
    #pragma unroll
    for (int i = 0; i < 4; i++)
        a_rowoff[i] = (uint32_t)((wm * 64 + i * 16 + (lid & 15)) * 128);
    #pragma unroll
    for (int j2 = 0; j2 < 4; j2++)
        b_rowoff[j2] = (uint32_t)((wn * 64 + j2 * 16 + (lid & 7) +
                                   ((lid >> 4) & 1) * 8) * 128);
    uint32_t a_ch[4], b_ch[4];
    #pragma unroll
    for (int q = 0; q < 4; q++) {
        a_ch[q] = (uint32_t)((((2 * q + (lid >> 4)) ^ (lid & 7)) * 16));
        b_ch[q] = (uint32_t)((((2 * q + ((lid >> 3) & 1)) ^ (lid & 7)) * 16));
    }

    float acc[4][8][4];
    #pragma unroll
    for (int i = 0; i < 4; i++)
        #pragma unroll
        for (int j = 0; j < 8; j++)
            #pragma unroll
            for (int r = 0; r < 4; r++)
                acc[i][j][r] = 0.0f;

    const int T0 = blockIdx.x;

    // Prologue: A ksteps 0,1 and B ksteps 0,1,2
    {
        const char* A0 = a_tile_ptr(T0);
        const char* B0 = b_tile_ptr(T0);
        load_half(tid, sb  + 0 * A_ST, A0);          CP_COMMIT();
        load_half(tid, sbB + 0 * B_ST, B0);          CP_COMMIT();
        load_half(tid, sb  + 1 * A_ST, A0 + 128);    CP_COMMIT();
        load_half(tid, sbB + 1 * B_ST, B0 + 128);    CP_COMMIT();
        load_half(tid, sbB + 2 * B_ST, B0 + 256);    CP_COMMIT();
    }

    const char* rA = a_tile_ptr(T0) + 2 * 128;
    const char* rB = b_tile_ptr(T0) + 3 * 128;
    bool liveA = true, liveB = true;

    uint32_t a_frag[2][4][4];
    uint32_t b_frag[2][4][4];
    int sA_cur = 0, sA_nxt = 2;    // mod 3
    int sB_cur = 0, sB_nxt = 3;    // mod 4

    #pragma unroll 1
    for (int T = T0; T < NTILES; T += GRID_CTAS) {
        const bool has_next = (T + GRID_CTAS) < NTILES;
        const char* AgN = has_next ? a_tile_ptr(T + GRID_CTAS) : rA;
        const char* BgN = has_next ? b_tile_ptr(T + GRID_CTAS) : rB;

        #pragma unroll 1
        for (int i = 0; i < KSTEPS; i++) {
            CP_WAIT3();
            __syncthreads();

            const uint32_t SA  = sb  + sA_cur * A_ST;
            const uint32_t SB  = sbB + sB_cur * B_ST;
            const uint32_t SAX = sb  + sA_nxt * A_ST;
            const uint32_t SBX = sbB + sB_nxt * B_ST;

            if (i == KSTEPS - 2) { rA = AgN; liveA = has_next; }   // A(i+2)
            if (i == KSTEPS - 3) { rB = BgN; liveB = has_next; }   // B(i+3)

            // q0 fragment prefetch FIRST: start the MMA dependency chain
            #pragma unroll
            for (int t4 = 0; t4 < 4; t4++)
                LDSM_X4(a_frag[0][t4][0], a_frag[0][t4][1],
                        a_frag[0][t4][2], a_frag[0][t4][3],
                        SA + a_rowoff[t4] + a_ch[0]);
            #pragma unroll
            for (int j2 = 0; j2 < 4; j2++)
                LDSM_X4(b_frag[0][j2][0], b_frag[0][j2][1],
                        b_frag[0][j2][2], b_frag[0][j2][3],
                        SB + b_rowoff[j2] + b_ch[0]);

            // A-refill group (for kstep i+2); ALWAYS commit for accounting
            if (liveA) load_half(tid, SAX, rA);
            CP_COMMIT();

            #pragma unroll
            for (int q = 0; q < 4; q++) {
                const int cur = q & 1, nxt = cur ^ 1;
                if (q < 3) {
                    #pragma unroll
                    for (int t4 = 0; t4 < 4; t4++)
                        LDSM_X4(a_frag[nxt][t4][0], a_frag[nxt][t4][1],
                                a_frag[nxt][t4][2], a_frag[nxt][t4][3],
                                SA + a_rowoff[t4] + a_ch[q + 1]);
                    #pragma unroll
                    for (int j2 = 0; j2 < 4; j2++)
                        LDSM_X4(b_frag[nxt][j2][0], b_frag[nxt][j2][1],
                                b_frag[nxt][j2][2], b_frag[nxt][j2][3],
                                SB + b_rowoff[j2] + b_ch[q + 1]);
                }
                if (q == 0) {
                    // B-refill group (for kstep i+3); ALWAYS commit
                    if (liveB) load_half(tid, SBX, rB);
                    CP_COMMIT();
                }
                #pragma unroll
                for (int t4 = 0; t4 < 4; t4++)
                    #pragma unroll
                    for (int j = 0; j < 8; j++)
                        mma16816(acc[t4][j], a_frag[cur][t4],
                                 &b_frag[cur][j >> 1][(j & 1) * 2]);
            }

            rA += 128;
            rB += 128;
            sA_cur = (sA_cur == A_RING - 1) ? 0 : sA_cur + 1;
            sA_nxt = (sA_nxt == A_RING - 1) ? 0 : sA_nxt + 1;
            sB_cur = (sB_cur == B_RING - 1) ? 0 : sB_cur + 1;
            sB_nxt = (sB_nxt == B_RING - 1) ? 0 : sB_nxt + 1;
        }

        // Epilogue for tile T (overlaps the next tile's in-flight loads)
        {
            const int m0 = (T >> 5) * BM;
            const int n0 = (T & (NTILES_X - 1)) * BN;
            const int g  = lid >> 2;
            const int tc = lid & 3;
            float* Cb = out + (size_t)(m0 + wm * 64) * N_DIM + n0 + wn * 64;
            #pragma unroll
            for (int t4 = 0; t4 < 4; t4++) {
                #pragma unroll
                for (int j = 0; j < 8; j++) {
                    float* p0 = Cb + (size_t)(t4 * 16 + g) * N_DIM + j * 8 + tc * 2;
                    float* p1 = p0 + 8 * N_DIM;
                    *reinterpret_cast<float2*>(p0) =
                        make_float2(acc[t4][j][0], acc[t4][j][1]);
                    *reinterpret_cast<float2*>(p1) =
                        make_float2(acc[t4][j][2], acc[t4][j][3]);
                    acc[t4][j][0] = 0.0f; acc[t4][j][1] = 0.0f;
                    acc[t4][j][2] = 0.0f; acc[t4][j][3] = 0.0f;
                }
            }
        }
    }
}

// ---------------------------------------------------------------------------
// Entry point. Inputs: x f32, grid_indices i32, scale f32, lut f32.
// Output: float32 [8192, 4096].
// ---------------------------------------------------------------------------
extern "C" void kernel_launch(void* const* d_in, const int* in_sizes, int n_in,
                              void* d_out, int out_size) {
    const float* x     = (const float*)d_in[0];
    const int*   idx   = (const int*)  d_in[1];
    const float* scale = (const float*)d_in[2];
    const float* lut   = (const float*)d_in[3];
    float* out = (float*)d_out;

    prep_kernel<<<PREP_BLOCKS, 256>>>(x, idx, scale, lut);

    cudaFuncSetAttribute(gemm_hmma_kernel,
                         cudaFuncAttributeMaxDynamicSharedMemorySize, SMEM_TOTAL);
    gemm_hmma_kernel<<<GRID_CTAS, 128, SMEM_TOTAL>>>(out);
}